// round 9
// baseline (speedup 1.0000x reference)
#include <cuda_runtime.h>
#include <cstdint>

// Fixed problem shape (per reference setup_inputs): N=500000 rows, D=300, G=8192.
#define D_FEAT 300
#define D_VEC4 75          // 300/4
#define G_MAX  8192
#define EPS    1e-6f

// ---------------------------------------------------------------------------
// Warp-parallel lower_bound over sorted seg[0..N): smallest i with seg[i] >=
// target. 33-ary search: 32 probes/round + ballot -> 4 dependent rounds for
// N=500000 (vs 19 for binary). All lanes return the same value.
// ---------------------------------------------------------------------------
__device__ __forceinline__ int warp_lower_bound(const int* __restrict__ seg,
                                                int N, int target)
{
    int lo = 0, hi = N;
    const int lane = threadIdx.x & 31;

    while (hi - lo > 32) {
        const long long span = (long long)(hi - lo);
        const int idx = lo + (int)(span * (lane + 1) / 33);   // in [lo, hi-1]
        const int v   = __ldg(&seg[idx]);
        const unsigned mask = __ballot_sync(0xffffffffu, v >= target);
        if (mask == 0) {
            lo = lo + (int)(span * 32 / 33) + 1;              // idx_31 + 1
        } else {
            const int first = __ffs(mask) - 1;
            hi = lo + (int)(span * (first + 1) / 33);         // idx_first
            if (first > 0) lo = lo + (int)(span * first / 33) + 1;
        }
    }
    // final linear probe of [lo, hi), span <= 32
    const int idx = lo + lane;
    const int v = (idx < hi) ? __ldg(&seg[idx]) : 0x7fffffff; // sentinel >= target
    const unsigned mask = __ballot_sync(0xffffffffu, v >= target);
    if (mask == 0) return hi;                                  // span==32, all < target
    return lo + __ffs(mask) - 1;
}

// ---------------------------------------------------------------------------
// Fused kernel (single launch): one block per segment. blockDim = 320
// (300 active = 75 float4-columns x 4 row-groups), 6 blocks/SM pinned.
// Warps 0/1 find the segment bounds via warp-parallel search (replaces the
// separate boundaries kernel + its launch gap). Then the proven R5/R8 body:
// Phase 1 sum/sumsq -> 75-thread coefficient section -> Phase 2 L2-hot
// re-stream with streaming cache hints.
// ---------------------------------------------------------------------------
__global__ __launch_bounds__(320, 6)
void fused_instnorm_kernel(const float4* __restrict__ x4,
                           const float*  __restrict__ weight,
                           const float*  __restrict__ bias,
                           const int*    __restrict__ seg,
                           float4*       __restrict__ out4,
                           int N)
{
    const int g = blockIdx.x;

    __shared__ int    s_bounds[2];
    __shared__ float4 s_sum[4][D_VEC4];
    __shared__ float4 s_sq [4][D_VEC4];
    __shared__ float4 s_a[D_VEC4];
    __shared__ float4 s_b[D_VEC4];

    const int tid = threadIdx.x;
    const int wid = tid >> 5;

    if (wid < 2) {
        const int r = warp_lower_bound(seg, N, g + wid);
        if ((tid & 31) == 0) s_bounds[wid] = r;
    }
    __syncthreads();

    const int start = s_bounds[0];
    const int cnt   = s_bounds[1] - start;

    const int c4 = tid % D_VEC4;   // float4 column (0..74)
    const int rg = tid / D_VEC4;   // row group (0..3) for tid < 300

    // ---------------- Phase 1: reduce sum / sumsq ----------------
    if (tid < 300) {
        float4 sum = make_float4(0.f, 0.f, 0.f, 0.f);
        float4 sq  = make_float4(0.f, 0.f, 0.f, 0.f);
        const float4* p = x4 + (size_t)start * D_VEC4 + c4;

        #pragma unroll 8
        for (int r = rg; r < cnt; r += 4) {
            const float4 v = p[(size_t)r * D_VEC4];
            sum.x += v.x; sum.y += v.y; sum.z += v.z; sum.w += v.w;
            sq.x = fmaf(v.x, v.x, sq.x);
            sq.y = fmaf(v.y, v.y, sq.y);
            sq.z = fmaf(v.z, v.z, sq.z);
            sq.w = fmaf(v.w, v.w, sq.w);
        }
        s_sum[rg][c4] = sum;
        s_sq [rg][c4] = sq;
    }
    __syncthreads();

    // ------- Coefficients: a = w*rsqrt(var+eps), b = bias - a*mean -------
    if (tid < D_VEC4) {
        float4 s0 = s_sum[0][tid], s1 = s_sum[1][tid],
               s2 = s_sum[2][tid], s3 = s_sum[3][tid];
        float4 q0 = s_sq[0][tid], q1 = s_sq[1][tid],
               q2 = s_sq[2][tid], q3 = s_sq[3][tid];

        float4 s, q;
        s.x = (s0.x + s1.x) + (s2.x + s3.x);
        s.y = (s0.y + s1.y) + (s2.y + s3.y);
        s.z = (s0.z + s1.z) + (s2.z + s3.z);
        s.w = (s0.w + s1.w) + (s2.w + s3.w);
        q.x = (q0.x + q1.x) + (q2.x + q3.x);
        q.y = (q0.y + q1.y) + (q2.y + q3.y);
        q.z = (q0.z + q1.z) + (q2.z + q3.z);
        q.w = (q0.w + q1.w) + (q2.w + q3.w);

        const float rc = 1.0f / (float)max(cnt, 1);
        const float4 w4 = __ldg(&((const float4*)weight)[tid]);
        const float4 b4 = __ldg(&((const float4*)bias)[tid]);

        float4 a, bb;
        {
            float mean = s.x * rc;
            float var  = fmaxf(fmaf(q.x, rc, -mean * mean), 0.f);
            a.x  = w4.x * rsqrtf(var + EPS);
            bb.x = b4.x - a.x * mean;
        }
        {
            float mean = s.y * rc;
            float var  = fmaxf(fmaf(q.y, rc, -mean * mean), 0.f);
            a.y  = w4.y * rsqrtf(var + EPS);
            bb.y = b4.y - a.y * mean;
        }
        {
            float mean = s.z * rc;
            float var  = fmaxf(fmaf(q.z, rc, -mean * mean), 0.f);
            a.z  = w4.z * rsqrtf(var + EPS);
            bb.z = b4.z - a.z * mean;
        }
        {
            float mean = s.w * rc;
            float var  = fmaxf(fmaf(q.w, rc, -mean * mean), 0.f);
            a.w  = w4.w * rsqrtf(var + EPS);
            bb.w = b4.w - a.w * mean;
        }
        s_a[tid] = a;
        s_b[tid] = bb;
    }
    __syncthreads();

    // ---------------- Phase 2: apply (segment rows L2-hot) ----------------
    if (tid < 300) {
        const float4 a  = s_a[c4];
        const float4 bb = s_b[c4];
        const float4* p = x4   + (size_t)start * D_VEC4 + c4;
        float4*       o = out4 + (size_t)start * D_VEC4 + c4;

        #pragma unroll 8
        for (int r = rg; r < cnt; r += 4) {
            const float4 v = __ldcs(&p[(size_t)r * D_VEC4]);  // last use: evict-first
            float4 res;
            res.x = fmaf(a.x, v.x, bb.x);
            res.y = fmaf(a.y, v.y, bb.y);
            res.z = fmaf(a.z, v.z, bb.z);
            res.w = fmaf(a.w, v.w, bb.w);
            __stcs(&o[(size_t)r * D_VEC4], res);              // streaming store
        }
    }
}

// ---------------------------------------------------------------------------
// Inputs (metadata order): tensor [N,300] f32, weight [300] f32,
// bias [300] f32, segment_ids [N] i32, num_graphs scalar i32 (= 8192).
// ---------------------------------------------------------------------------
extern "C" void kernel_launch(void* const* d_in, const int* in_sizes, int n_in,
                              void* d_out, int out_size)
{
    const float* tensor = (const float*)d_in[0];
    const float* weight = (const float*)d_in[1];
    const float* bias   = (const float*)d_in[2];
    const int*   seg    = (const int*)d_in[3];
    const int N = in_sizes[3];

    fused_instnorm_kernel<<<G_MAX, 320>>>((const float4*)tensor, weight, bias,
                                          seg, (float4*)d_out, N);
}

// round 10
// speedup vs baseline: 1.0021x; 1.0021x over previous
#include <cuda_runtime.h>
#include <cstdint>

// Fixed problem shape (per reference setup_inputs): N=500000 rows, D=300, G=8192.
#define D_FEAT 300
#define D_VEC4 75          // 300/4
#define G_MAX  8192
#define EPS    1e-6f

// ---------------------------------------------------------------------------
// 33-ary warp lower_bound on [lo, hi], precondition: answer in [lo, hi]
// (f(lo-1) < target, and f(hi) >= target or hi is the logical end).
// All lanes return the same value.
// ---------------------------------------------------------------------------
__device__ __forceinline__ int warp_lb_33(const int* __restrict__ seg,
                                          int lo, int hi, int target, int lane)
{
    while (hi - lo > 32) {
        const long long span = (long long)(hi - lo);
        const int idx = lo + (int)(span * (lane + 1) / 33);   // in [lo, hi-1]
        const int v   = __ldg(&seg[idx]);
        const unsigned mask = __ballot_sync(0xffffffffu, v >= target);
        if (mask == 0) {
            lo = lo + (int)(span * 32 / 33) + 1;
        } else {
            const int first = __ffs(mask) - 1;
            hi = lo + (int)(span * (first + 1) / 33);
            if (first > 0) lo = lo + (int)(span * first / 33) + 1;
        }
    }
    const int idx = lo + lane;
    const int v = (idx < hi) ? __ldg(&seg[idx]) : 0x7fffffff;  // sentinel
    const unsigned mask = __ballot_sync(0xffffffffu, v >= target);
    if (mask == 0) return hi;
    return lo + __ffs(mask) - 1;
}

// ---------------------------------------------------------------------------
// Hint-seeded warp lower_bound: one bracketing round (32 probes, stride 512,
// centered at guess -> covers +-8192 rows ~= 23 sigma of segment-start
// deviation), then 33-ary on a <=512 window -> <=16 -> linear.
// 3 dependent probe rounds on the common path; correct fallback otherwise.
// ---------------------------------------------------------------------------
__device__ __forceinline__ int warp_lower_bound_hint(const int* __restrict__ seg,
                                                     int N, int target, int guess)
{
    const int lane = threadIdx.x & 31;
    const int S = 512;

    const int pos = guess + (lane - 16) * S;
    int v;
    if (pos < 0)        v = (int)0x80000000;        // -inf: before array
    else if (pos >= N)  v = 0x7fffffff;             // +inf: past array
    else                v = __ldg(&seg[pos]);

    const unsigned mask = __ballot_sync(0xffffffffu, v >= target);

    int lo, hi;
    if (mask == 0) {
        // all probes < target (implies guess+15S < N): answer in (guess+15S, N]
        lo = guess + 15 * S + 1;
        if (lo < 0) lo = 0;
        hi = N;
    } else {
        const int j  = __ffs(mask) - 1;
        int pj = guess + (j - 16) * S;
        if (pj > N) pj = N;
        hi = pj;                                    // f(pj) >= target (or pj==N)
        if (j == 0) {
            lo = 0;                                 // unbracketed left: rare
        } else {
            lo = pj - S + 1;                        // f(pj - S) < target (probed)
            if (lo < 0) lo = 0;
        }
    }
    return warp_lb_33(seg, lo, hi, target, lane);
}

// ---------------------------------------------------------------------------
// Fused kernel (single launch): one block per segment. blockDim = 320
// (300 active = 75 float4-columns x 4 row-groups), 6 blocks/SM pinned.
// Warps 0/1 resolve the two segment bounds via the hint-seeded search (3
// dependent L2 probes), then the proven R8 body: phase-1 sum/sumsq,
// 75-thread coefficient section, phase-2 L2-hot re-stream with streaming
// cache hints.
// ---------------------------------------------------------------------------
__global__ __launch_bounds__(320, 6)
void fused_instnorm_kernel(const float4* __restrict__ x4,
                           const float*  __restrict__ weight,
                           const float*  __restrict__ bias,
                           const int*    __restrict__ seg,
                           float4*       __restrict__ out4,
                           int N)
{
    const int g = blockIdx.x;

    __shared__ int    s_bounds[2];
    __shared__ float4 s_sum[4][D_VEC4];
    __shared__ float4 s_sq [4][D_VEC4];
    __shared__ float4 s_a[D_VEC4];
    __shared__ float4 s_b[D_VEC4];

    const int tid = threadIdx.x;
    const int wid = tid >> 5;

    if (wid < 2) {
        const int target = g + wid;
        const int guess  = (int)((long long)target * N / G_MAX);
        const int r = warp_lower_bound_hint(seg, N, target, guess);
        if ((tid & 31) == 0) s_bounds[wid] = r;
    }
    __syncthreads();

    const int start = s_bounds[0];
    const int cnt   = s_bounds[1] - start;

    const int c4 = tid % D_VEC4;   // float4 column (0..74)
    const int rg = tid / D_VEC4;   // row group (0..3) for tid < 300

    // ---------------- Phase 1: reduce sum / sumsq ----------------
    if (tid < 300) {
        float4 sum = make_float4(0.f, 0.f, 0.f, 0.f);
        float4 sq  = make_float4(0.f, 0.f, 0.f, 0.f);
        const float4* p = x4 + (size_t)start * D_VEC4 + c4;

        #pragma unroll 8
        for (int r = rg; r < cnt; r += 4) {
            const float4 v = p[(size_t)r * D_VEC4];
            sum.x += v.x; sum.y += v.y; sum.z += v.z; sum.w += v.w;
            sq.x = fmaf(v.x, v.x, sq.x);
            sq.y = fmaf(v.y, v.y, sq.y);
            sq.z = fmaf(v.z, v.z, sq.z);
            sq.w = fmaf(v.w, v.w, sq.w);
        }
        s_sum[rg][c4] = sum;
        s_sq [rg][c4] = sq;
    }
    __syncthreads();

    // ------- Coefficients: a = w*rsqrt(var+eps), b = bias - a*mean -------
    if (tid < D_VEC4) {
        float4 s0 = s_sum[0][tid], s1 = s_sum[1][tid],
               s2 = s_sum[2][tid], s3 = s_sum[3][tid];
        float4 q0 = s_sq[0][tid], q1 = s_sq[1][tid],
               q2 = s_sq[2][tid], q3 = s_sq[3][tid];

        float4 s, q;
        s.x = (s0.x + s1.x) + (s2.x + s3.x);
        s.y = (s0.y + s1.y) + (s2.y + s3.y);
        s.z = (s0.z + s1.z) + (s2.z + s3.z);
        s.w = (s0.w + s1.w) + (s2.w + s3.w);
        q.x = (q0.x + q1.x) + (q2.x + q3.x);
        q.y = (q0.y + q1.y) + (q2.y + q3.y);
        q.z = (q0.z + q1.z) + (q2.z + q3.z);
        q.w = (q0.w + q1.w) + (q2.w + q3.w);

        const float rc = 1.0f / (float)max(cnt, 1);
        const float4 w4 = __ldg(&((const float4*)weight)[tid]);
        const float4 b4 = __ldg(&((const float4*)bias)[tid]);

        float4 a, bb;
        {
            float mean = s.x * rc;
            float var  = fmaxf(fmaf(q.x, rc, -mean * mean), 0.f);
            a.x  = w4.x * rsqrtf(var + EPS);
            bb.x = b4.x - a.x * mean;
        }
        {
            float mean = s.y * rc;
            float var  = fmaxf(fmaf(q.y, rc, -mean * mean), 0.f);
            a.y  = w4.y * rsqrtf(var + EPS);
            bb.y = b4.y - a.y * mean;
        }
        {
            float mean = s.z * rc;
            float var  = fmaxf(fmaf(q.z, rc, -mean * mean), 0.f);
            a.z  = w4.z * rsqrtf(var + EPS);
            bb.z = b4.z - a.z * mean;
        }
        {
            float mean = s.w * rc;
            float var  = fmaxf(fmaf(q.w, rc, -mean * mean), 0.f);
            a.w  = w4.w * rsqrtf(var + EPS);
            bb.w = b4.w - a.w * mean;
        }
        s_a[tid] = a;
        s_b[tid] = bb;
    }
    __syncthreads();

    // ---------------- Phase 2: apply (segment rows L2-hot) ----------------
    if (tid < 300) {
        const float4 a  = s_a[c4];
        const float4 bb = s_b[c4];
        const float4* p = x4   + (size_t)start * D_VEC4 + c4;
        float4*       o = out4 + (size_t)start * D_VEC4 + c4;

        #pragma unroll 8
        for (int r = rg; r < cnt; r += 4) {
            const float4 v = __ldcs(&p[(size_t)r * D_VEC4]);  // last use: evict-first
            float4 res;
            res.x = fmaf(a.x, v.x, bb.x);
            res.y = fmaf(a.y, v.y, bb.y);
            res.z = fmaf(a.z, v.z, bb.z);
            res.w = fmaf(a.w, v.w, bb.w);
            __stcs(&o[(size_t)r * D_VEC4], res);              // streaming store
        }
    }
}

// ---------------------------------------------------------------------------
// Inputs (metadata order): tensor [N,300] f32, weight [300] f32,
// bias [300] f32, segment_ids [N] i32, num_graphs scalar i32 (= 8192).
// ---------------------------------------------------------------------------
extern "C" void kernel_launch(void* const* d_in, const int* in_sizes, int n_in,
                              void* d_out, int out_size)
{
    const float* tensor = (const float*)d_in[0];
    const float* weight = (const float*)d_in[1];
    const float* bias   = (const float*)d_in[2];
    const int*   seg    = (const int*)d_in[3];
    const int N = in_sizes[3];

    fused_instnorm_kernel<<<G_MAX, 320>>>((const float4*)tensor, weight, bias,
                                          seg, (float4*)d_out, N);
}

// round 11
// speedup vs baseline: 1.0324x; 1.0303x over previous
#include <cuda_runtime.h>
#include <cstdint>

// Fixed problem shape (per reference setup_inputs): N=500000 rows, D=300, G=8192.
#define D_FEAT 300
#define D_VEC4 75          // 300/4
#define G_MAX  8192
#define EPS    1e-6f

// Precomputed segment boundaries: offs[g] = first row of segment g, offs[G]=N.
__device__ int g_offs[G_MAX + 1];

// ---------------------------------------------------------------------------
// Kernel 0: segment boundary precompute (segment_ids sorted), int4-vectorized.
// offs[g] = lower_bound(seg, g). Each thread owns rows 4i..4i+3 and fills
// offsets for every boundary it straddles; total fill work across threads == G.
// Full-grid parallelism makes this ~3 us total — cheaper than any per-block
// in-kernel search (R9: +10.6 us, R10: +8.3 us vs the ~3-4 us this costs).
// ---------------------------------------------------------------------------
__global__ __launch_bounds__(256)
void boundaries_kernel(const int4* __restrict__ seg4, int N)
{
    const int i = blockIdx.x * blockDim.x + threadIdx.x;
    const int N4 = N >> 2;
    if (i >= N4) return;

    const int4 v = seg4[i];
    const int prev = (i == 0) ? -1 : __ldg(&((const int*)seg4)[4 * i - 1]);

    const int base = 4 * i;
    for (int g = prev + 1; g <= v.x; ++g) g_offs[g] = base;
    for (int g = v.x + 1; g <= v.y; ++g) g_offs[g] = base + 1;
    for (int g = v.y + 1; g <= v.z; ++g) g_offs[g] = base + 2;
    for (int g = v.z + 1; g <= v.w; ++g) g_offs[g] = base + 3;
    if (base + 4 == N) {
        for (int g = v.w + 1; g <= G_MAX; ++g) g_offs[g] = N;
    }
}

// ---------------------------------------------------------------------------
// Fused kernel (proven optimum across R2-R10): one block per segment.
// blockDim = 320 (300 active = 75 float4-columns x 4 row-groups).
// __launch_bounds__(320, 6) pins regs <= 34 -> 6 blocks/SM residency, which
// supplies the MLP that saturates HBM (R4 showed the residency cliff).
// Phase 1: per-feature sum/sumsq (float4 loads, 4-way row parallelism).
// 75-thread coefficient section (R7 showed redundant per-thread coefficient
// computation degrades the streaming schedule).
// Phase 2: re-stream the segment (L2-hot from phase 1) applying out = a*x+b
// with streaming cache hints (evict-first loads, streaming stores).
// Achieves the 1.2 GB DRAM traffic floor at ~75% of HBM spec (mixed-R:W
// ceiling); main kernel ~202 us.
// ---------------------------------------------------------------------------
__global__ __launch_bounds__(320, 6)
void fused_instnorm_kernel(const float4* __restrict__ x4,
                           const float*  __restrict__ weight,
                           const float*  __restrict__ bias,
                           float4*       __restrict__ out4)
{
    const int g = blockIdx.x;

    __shared__ float4 s_sum[4][D_VEC4];
    __shared__ float4 s_sq [4][D_VEC4];
    __shared__ float4 s_a[D_VEC4];
    __shared__ float4 s_b[D_VEC4];

    const int start = g_offs[g];
    const int cnt   = g_offs[g + 1] - start;
    const int tid   = threadIdx.x;

    const int c4 = tid % D_VEC4;   // float4 column (0..74)
    const int rg = tid / D_VEC4;   // row group (0..3) for tid < 300

    // ---------------- Phase 1: reduce sum / sumsq ----------------
    if (tid < 300) {
        float4 sum = make_float4(0.f, 0.f, 0.f, 0.f);
        float4 sq  = make_float4(0.f, 0.f, 0.f, 0.f);
        const float4* p = x4 + (size_t)start * D_VEC4 + c4;

        #pragma unroll 8
        for (int r = rg; r < cnt; r += 4) {
            const float4 v = p[(size_t)r * D_VEC4];
            sum.x += v.x; sum.y += v.y; sum.z += v.z; sum.w += v.w;
            sq.x = fmaf(v.x, v.x, sq.x);
            sq.y = fmaf(v.y, v.y, sq.y);
            sq.z = fmaf(v.z, v.z, sq.z);
            sq.w = fmaf(v.w, v.w, sq.w);
        }
        s_sum[rg][c4] = sum;
        s_sq [rg][c4] = sq;
    }
    __syncthreads();

    // ------- Coefficients: a = w*rsqrt(var+eps), b = bias - a*mean -------
    if (tid < D_VEC4) {
        float4 s0 = s_sum[0][tid], s1 = s_sum[1][tid],
               s2 = s_sum[2][tid], s3 = s_sum[3][tid];
        float4 q0 = s_sq[0][tid], q1 = s_sq[1][tid],
               q2 = s_sq[2][tid], q3 = s_sq[3][tid];

        float4 s, q;
        s.x = (s0.x + s1.x) + (s2.x + s3.x);
        s.y = (s0.y + s1.y) + (s2.y + s3.y);
        s.z = (s0.z + s1.z) + (s2.z + s3.z);
        s.w = (s0.w + s1.w) + (s2.w + s3.w);
        q.x = (q0.x + q1.x) + (q2.x + q3.x);
        q.y = (q0.y + q1.y) + (q2.y + q3.y);
        q.z = (q0.z + q1.z) + (q2.z + q3.z);
        q.w = (q0.w + q1.w) + (q2.w + q3.w);

        const float rc = 1.0f / (float)max(cnt, 1);
        const float4 w4 = __ldg(&((const float4*)weight)[tid]);
        const float4 b4 = __ldg(&((const float4*)bias)[tid]);

        float4 a, bb;
        {
            float mean = s.x * rc;
            float var  = fmaxf(fmaf(q.x, rc, -mean * mean), 0.f);
            a.x  = w4.x * rsqrtf(var + EPS);
            bb.x = b4.x - a.x * mean;
        }
        {
            float mean = s.y * rc;
            float var  = fmaxf(fmaf(q.y, rc, -mean * mean), 0.f);
            a.y  = w4.y * rsqrtf(var + EPS);
            bb.y = b4.y - a.y * mean;
        }
        {
            float mean = s.z * rc;
            float var  = fmaxf(fmaf(q.z, rc, -mean * mean), 0.f);
            a.z  = w4.z * rsqrtf(var + EPS);
            bb.z = b4.z - a.z * mean;
        }
        {
            float mean = s.w * rc;
            float var  = fmaxf(fmaf(q.w, rc, -mean * mean), 0.f);
            a.w  = w4.w * rsqrtf(var + EPS);
            bb.w = b4.w - a.w * mean;
        }
        s_a[tid] = a;
        s_b[tid] = bb;
    }
    __syncthreads();

    // ---------------- Phase 2: apply (segment rows L2-hot) ----------------
    if (tid < 300) {
        const float4 a  = s_a[c4];
        const float4 bb = s_b[c4];
        const float4* p = x4   + (size_t)start * D_VEC4 + c4;
        float4*       o = out4 + (size_t)start * D_VEC4 + c4;

        #pragma unroll 8
        for (int r = rg; r < cnt; r += 4) {
            const float4 v = __ldcs(&p[(size_t)r * D_VEC4]);  // last use: evict-first
            float4 res;
            res.x = fmaf(a.x, v.x, bb.x);
            res.y = fmaf(a.y, v.y, bb.y);
            res.z = fmaf(a.z, v.z, bb.z);
            res.w = fmaf(a.w, v.w, bb.w);
            __stcs(&o[(size_t)r * D_VEC4], res);              // streaming store
        }
    }
}

// ---------------------------------------------------------------------------
// Inputs (metadata order): tensor [N,300] f32, weight [300] f32,
// bias [300] f32, segment_ids [N] i32, num_graphs scalar i32 (= 8192).
// ---------------------------------------------------------------------------
extern "C" void kernel_launch(void* const* d_in, const int* in_sizes, int n_in,
                              void* d_out, int out_size)
{
    const float* tensor = (const float*)d_in[0];
    const float* weight = (const float*)d_in[1];
    const float* bias   = (const float*)d_in[2];
    const int*   seg    = (const int*)d_in[3];
    const int N = in_sizes[3];

    const int n4 = N >> 2;
    boundaries_kernel<<<(n4 + 255) / 256, 256>>>((const int4*)seg, N);
    fused_instnorm_kernel<<<G_MAX, 320>>>((const float4*)tensor, weight, bias,
                                          (float4*)d_out);
}

// round 12
// speedup vs baseline: 1.0335x; 1.0011x over previous
#include <cuda_runtime.h>
#include <cstdint>

// Fixed problem shape (per reference setup_inputs): N=500000 rows, D=300, G=8192.
#define D_FEAT 300
#define D_VEC4 75          // 300/4
#define G_MAX  8192
#define EPS    1e-6f

// Precomputed segment boundaries: offs[g] = first row of segment g, offs[G]=N.
__device__ int g_offs[G_MAX + 1];

// ---------------------------------------------------------------------------
// Kernel 0: segment boundary precompute (segment_ids sorted), int4-vectorized.
// offs[g] = lower_bound(seg, g). Each thread owns rows 4i..4i+3 and fills
// offsets for every boundary it straddles; total fill work across threads == G.
// ---------------------------------------------------------------------------
__global__ __launch_bounds__(256)
void boundaries_kernel(const int4* __restrict__ seg4, int N)
{
    const int i = blockIdx.x * blockDim.x + threadIdx.x;
    const int N4 = N >> 2;
    if (i >= N4) return;

    const int4 v = seg4[i];
    const int prev = (i == 0) ? -1 : __ldg(&((const int*)seg4)[4 * i - 1]);

    const int base = 4 * i;
    for (int g = prev + 1; g <= v.x; ++g) g_offs[g] = base;
    for (int g = v.x + 1; g <= v.y; ++g) g_offs[g] = base + 1;
    for (int g = v.y + 1; g <= v.z; ++g) g_offs[g] = base + 2;
    for (int g = v.z + 1; g <= v.w; ++g) g_offs[g] = base + 3;
    if (base + 4 == N) {
        for (int g = v.w + 1; g <= G_MAX; ++g) g_offs[g] = N;
    }
}

// ---------------------------------------------------------------------------
// Fused kernel (R8 structure — proven optimum): one block per segment.
// blockDim = 320 (300 active = 75 float4-columns x 4 row-groups), 6 blocks/SM.
// Cache policy (this round's change):
//   phase-1 loads : __ldcg  — L2-only; L1 allocation is pure waste since the
//                   per-SM working set (~440 KB) exceeds L1 and phase 2 never
//                   hits L1 anyway.
//   phase-2 loads : __ldlu  — last-use; line dies in L2 at the read, freeing
//                   capacity for other blocks' phase-1 fills earlier.
//   stores        : __stcs  — streaming, never re-read.
// ---------------------------------------------------------------------------
__global__ __launch_bounds__(320, 6)
void fused_instnorm_kernel(const float4* __restrict__ x4,
                           const float*  __restrict__ weight,
                           const float*  __restrict__ bias,
                           float4*       __restrict__ out4)
{
    const int g = blockIdx.x;

    __shared__ float4 s_sum[4][D_VEC4];
    __shared__ float4 s_sq [4][D_VEC4];
    __shared__ float4 s_a[D_VEC4];
    __shared__ float4 s_b[D_VEC4];

    const int start = g_offs[g];
    const int cnt   = g_offs[g + 1] - start;
    const int tid   = threadIdx.x;

    const int c4 = tid % D_VEC4;   // float4 column (0..74)
    const int rg = tid / D_VEC4;   // row group (0..3) for tid < 300

    // ---------------- Phase 1: reduce sum / sumsq ----------------
    if (tid < 300) {
        float4 sum = make_float4(0.f, 0.f, 0.f, 0.f);
        float4 sq  = make_float4(0.f, 0.f, 0.f, 0.f);
        const float4* p = x4 + (size_t)start * D_VEC4 + c4;

        #pragma unroll 8
        for (int r = rg; r < cnt; r += 4) {
            const float4 v = __ldcg(&p[(size_t)r * D_VEC4]);  // L2-only fill
            sum.x += v.x; sum.y += v.y; sum.z += v.z; sum.w += v.w;
            sq.x = fmaf(v.x, v.x, sq.x);
            sq.y = fmaf(v.y, v.y, sq.y);
            sq.z = fmaf(v.z, v.z, sq.z);
            sq.w = fmaf(v.w, v.w, sq.w);
        }
        s_sum[rg][c4] = sum;
        s_sq [rg][c4] = sq;
    }
    __syncthreads();

    // ------- Coefficients: a = w*rsqrt(var+eps), b = bias - a*mean -------
    if (tid < D_VEC4) {
        float4 s0 = s_sum[0][tid], s1 = s_sum[1][tid],
               s2 = s_sum[2][tid], s3 = s_sum[3][tid];
        float4 q0 = s_sq[0][tid], q1 = s_sq[1][tid],
               q2 = s_sq[2][tid], q3 = s_sq[3][tid];

        float4 s, q;
        s.x = (s0.x + s1.x) + (s2.x + s3.x);
        s.y = (s0.y + s1.y) + (s2.y + s3.y);
        s.z = (s0.z + s1.z) + (s2.z + s3.z);
        s.w = (s0.w + s1.w) + (s2.w + s3.w);
        q.x = (q0.x + q1.x) + (q2.x + q3.x);
        q.y = (q0.y + q1.y) + (q2.y + q3.y);
        q.z = (q0.z + q1.z) + (q2.z + q3.z);
        q.w = (q0.w + q1.w) + (q2.w + q3.w);

        const float rc = 1.0f / (float)max(cnt, 1);
        const float4 w4 = __ldg(&((const float4*)weight)[tid]);
        const float4 b4 = __ldg(&((const float4*)bias)[tid]);

        float4 a, bb;
        {
            float mean = s.x * rc;
            float var  = fmaxf(fmaf(q.x, rc, -mean * mean), 0.f);
            a.x  = w4.x * rsqrtf(var + EPS);
            bb.x = b4.x - a.x * mean;
        }
        {
            float mean = s.y * rc;
            float var  = fmaxf(fmaf(q.y, rc, -mean * mean), 0.f);
            a.y  = w4.y * rsqrtf(var + EPS);
            bb.y = b4.y - a.y * mean;
        }
        {
            float mean = s.z * rc;
            float var  = fmaxf(fmaf(q.z, rc, -mean * mean), 0.f);
            a.z  = w4.z * rsqrtf(var + EPS);
            bb.z = b4.z - a.z * mean;
        }
        {
            float mean = s.w * rc;
            float var  = fmaxf(fmaf(q.w, rc, -mean * mean), 0.f);
            a.w  = w4.w * rsqrtf(var + EPS);
            bb.w = b4.w - a.w * mean;
        }
        s_a[tid] = a;
        s_b[tid] = bb;
    }
    __syncthreads();

    // ---------------- Phase 2: apply (segment rows L2-hot) ----------------
    if (tid < 300) {
        const float4 a  = s_a[c4];
        const float4 bb = s_b[c4];
        const float4* p = x4   + (size_t)start * D_VEC4 + c4;
        float4*       o = out4 + (size_t)start * D_VEC4 + c4;

        #pragma unroll 8
        for (int r = rg; r < cnt; r += 4) {
            const float4 v = __ldlu(&p[(size_t)r * D_VEC4]);  // last use: line dies
            float4 res;
            res.x = fmaf(a.x, v.x, bb.x);
            res.y = fmaf(a.y, v.y, bb.y);
            res.z = fmaf(a.z, v.z, bb.z);
            res.w = fmaf(a.w, v.w, bb.w);
            __stcs(&o[(size_t)r * D_VEC4], res);              // streaming store
        }
    }
}

// ---------------------------------------------------------------------------
// Inputs (metadata order): tensor [N,300] f32, weight [300] f32,
// bias [300] f32, segment_ids [N] i32, num_graphs scalar i32 (= 8192).
// ---------------------------------------------------------------------------
extern "C" void kernel_launch(void* const* d_in, const int* in_sizes, int n_in,
                              void* d_out, int out_size)
{
    const float* tensor = (const float*)d_in[0];
    const float* weight = (const float*)d_in[1];
    const float* bias   = (const float*)d_in[2];
    const int*   seg    = (const int*)d_in[3];
    const int N = in_sizes[3];

    const int n4 = N >> 2;
    boundaries_kernel<<<(n4 + 255) / 256, 256>>>((const int4*)seg, N);
    fused_instnorm_kernel<<<G_MAX, 320>>>((const float4*)tensor, weight, bias,
                                          (float4*)d_out);
}